// round 16
// baseline (speedup 1.0000x reference)
#include <cuda_runtime.h>
#include <cuda_fp16.h>
#include <math.h>
#include <stdint.h>

// Problem constants
#define LNUM 4
#define BB   64
#define TT   256
#define HH   1024
#define DD   1024
#define G4   4096
#define NBLK 128

// ---------------- scratch (device globals) ----------------
__device__ float g_gx[(size_t)TT * BB * G4];               // [t][nt][b][32] block-local layout
__device__ unsigned long long g_barctr;

__device__ __half g_act[(size_t)BB * TT * HH];             // fp16 single-term activations
__device__ __half g_h[2][BB * HH];                         // h ping-pong, fp16 single
__device__ __half g_wih_h[(size_t)LNUM * G4 * HH];
__device__ __half g_wih_l[(size_t)LNUM * G4 * HH];
__device__ __half g_whh_h[(size_t)LNUM * G4 * HH];
__device__ __half g_whh_l[(size_t)LNUM * G4 * HH];
__device__ __half g_wout_h[(size_t)DD * HH];
__device__ __half g_wout_l[(size_t)DD * HH];

// ---------------- helpers ----------------
__device__ __forceinline__ uint32_t smem_u32(const void* p) {
    uint32_t a;
    asm("{ .reg .u64 t; cvta.to.shared.u64 t, %1; cvt.u32.u64 %0, t; }" : "=r"(a) : "l"(p));
    return a;
}
__device__ __forceinline__ float sigmoidf_(float x) { return 1.0f / (1.0f + expf(-x)); }

__device__ __forceinline__ void ldm_x4(uint32_t& r0, uint32_t& r1, uint32_t& r2, uint32_t& r3, uint32_t addr) {
    asm volatile("ldmatrix.sync.aligned.m8n8.x4.shared.b16 {%0,%1,%2,%3}, [%4];"
                 : "=r"(r0), "=r"(r1), "=r"(r2), "=r"(r3) : "r"(addr));
}
__device__ __forceinline__ void mma16816(float* d, const uint32_t* a, uint32_t b0, uint32_t b1) {
    asm volatile("mma.sync.aligned.m16n8k16.row.col.f32.f16.f16.f32 "
                 "{%0,%1,%2,%3}, {%4,%5,%6,%7}, {%8,%9}, {%0,%1,%2,%3};"
                 : "+f"(d[0]), "+f"(d[1]), "+f"(d[2]), "+f"(d[3])
                 : "r"(a[0]), "r"(a[1]), "r"(a[2]), "r"(a[3]), "r"(b0), "r"(b1));
}
__device__ __forceinline__ void cp16(uint32_t saddr, const void* gaddr) {
    asm volatile("cp.async.cg.shared.global [%0], [%1], 16;" :: "r"(saddr), "l"(gaddr));
}

// ---------------- grid barrier (monotonic ticket, flat — proven best) ----------------
__device__ __forceinline__ void grid_barrier() {
    __syncthreads();
    if (threadIdx.x == 0) {
        __threadfence();
        unsigned long long ticket = atomicAdd(&g_barctr, 1ull);
        unsigned long long target = (ticket / NBLK + 1ull) * NBLK;
        while (*(volatile unsigned long long*)&g_barctr < target) __nanosleep(32);
        __threadfence();
    }
    __syncthreads();
}

// ---------------- fp32 -> fp16 hi/lo weight split ----------------
__global__ void __launch_bounds__(256)
splitw_f16(const float* __restrict__ in, __half* __restrict__ hi,
           __half* __restrict__ lo, int n4)
{
    int i = blockIdx.x * blockDim.x + threadIdx.x;
    if (i >= n4) return;
    float4 v = reinterpret_cast<const float4*>(in)[i];
    __half h0 = __float2half(v.x), h1 = __float2half(v.y);
    __half h2 = __float2half(v.z), h3 = __float2half(v.w);
    __half l0 = __float2half(v.x - __half2float(h0));
    __half l1 = __float2half(v.y - __half2float(h1));
    __half l2 = __float2half(v.z - __half2float(h2));
    __half l3 = __float2half(v.w - __half2float(h3));
    __half2 hv0 = {h0, h1}, hv1 = {h2, h3};
    __half2 lv0 = {l0, l1}, lv1 = {l2, l3};
    reinterpret_cast<__half2*>(hi)[2 * i] = hv0;
    reinterpret_cast<__half2*>(hi)[2 * i + 1] = hv1;
    reinterpret_cast<__half2*>(lo)[2 * i] = lv0;
    reinterpret_cast<__half2*>(lo)[2 * i + 1] = lv1;
}

// ---------------- fp32 -> fp16 single conversion ----------------
__global__ void __launch_bounds__(256)
conv_f16(const float* __restrict__ in, __half* __restrict__ out, int n4)
{
    int i = blockIdx.x * blockDim.x + threadIdx.x;
    if (i >= n4) return;
    float4 v = reinterpret_cast<const float4*>(in)[i];
    __half2 o0 = {__float2half(v.x), __float2half(v.y)};
    __half2 o1 = {__float2half(v.z), __float2half(v.w)};
    reinterpret_cast<__half2*>(out)[2 * i] = o0;
    reinterpret_cast<__half2*>(out)[2 * i + 1] = o1;
}

// ---------------- HMMA fp16 GEMM: C = A*(Wh+Wl)^T + bias (fp32 acc, 2 CTAs/SM) ----------------
#define GK      1024
#define PITCH   40
#define TILE_B2 10240

template<int MODE>
__global__ void __launch_bounds__(256, 2)
gemm_hmma(const __half* __restrict__ A,
          const __half* __restrict__ Bh, const __half* __restrict__ Bl,
          const float* __restrict__ bias, float* __restrict__ C)
{
    extern __shared__ __align__(16) char smem[];
    const uint32_t s0 = smem_u32(smem);

    const int tid = threadIdx.x;
    const int wid = tid >> 5;
    const int lid = tid & 31;
    const int m0 = blockIdx.x * 128;
    const int n0 = blockIdx.y * 128;
    const int warp_m = (wid >> 1) * 32;
    const int warp_n = (wid & 1) * 64;

    auto preload = [&](int s, int kb) {
        const uint32_t base = s0 + (uint32_t)s * (3 * TILE_B2);
#pragma unroll
        for (int j = 0; j < 6; j++) {
            int c = tid + j * 256;
            int tsel = c >> 9, idx = c & 511;
            int row = idx >> 2, seg = idx & 3;
            const __half* src;
            if (tsel == 0)      src = A  + (size_t)(m0 + row) * GK + kb + seg * 8;
            else if (tsel == 1) src = Bh + (size_t)(n0 + row) * GK + kb + seg * 8;
            else                src = Bl + (size_t)(n0 + row) * GK + kb + seg * 8;
            uint32_t dst = base + (uint32_t)tsel * TILE_B2 + (uint32_t)(row * 80 + seg * 16);
            cp16(dst, src);
        }
        asm volatile("cp.async.commit_group;" ::: "memory");
    };

    const int q = lid >> 3, i8 = lid & 7;
    const int a_row = (q & 1) * 8 + i8;
    const int a_k8  = (q >> 1) * 8;
    const int b_row = (q >> 1) * 8 + i8;
    const int b_k8  = (q & 1) * 8;

    float acc[2][8][4];
#pragma unroll
    for (int mt = 0; mt < 2; mt++)
#pragma unroll
        for (int nt = 0; nt < 8; nt++)
#pragma unroll
            for (int e = 0; e < 4; e++) acc[mt][nt][e] = 0.0f;

    constexpr int NIT = 32;
    preload(0, 0);

#pragma unroll 1
    for (int it = 0; it < NIT; it++) {
        const int s = it & 1;
        if (it + 1 < NIT) {
            preload(s ^ 1, (it + 1) * 32);
            asm volatile("cp.async.wait_group 1;" ::: "memory");
        } else {
            asm volatile("cp.async.wait_group 0;" ::: "memory");
        }
        __syncthreads();

        const uint32_t sa  = s0 + (uint32_t)s * (3 * TILE_B2);
        const uint32_t sbh = sa + TILE_B2;
        const uint32_t sbl = sa + 2 * TILE_B2;
#pragma unroll
        for (int kk = 0; kk < 32; kk += 16) {
            uint32_t a[2][4], bh[4][4], bl[4][4];
#pragma unroll
            for (int mt = 0; mt < 2; mt++) {
                uint32_t addr = sa + (uint32_t)((warp_m + mt * 16 + a_row) * 80 + (kk + a_k8) * 2);
                ldm_x4(a[mt][0], a[mt][1], a[mt][2], a[mt][3], addr);
            }
#pragma unroll
            for (int ng = 0; ng < 4; ng++) {
                uint32_t off = (uint32_t)((warp_n + ng * 16 + b_row) * 80 + (kk + b_k8) * 2);
                ldm_x4(bh[ng][0], bh[ng][1], bh[ng][2], bh[ng][3], sbh + off);
                ldm_x4(bl[ng][0], bl[ng][1], bl[ng][2], bl[ng][3], sbl + off);
            }
#pragma unroll
            for (int mt = 0; mt < 2; mt++)
#pragma unroll
                for (int ng = 0; ng < 4; ng++) {
                    mma16816(acc[mt][2 * ng + 0], a[mt], bh[ng][0], bh[ng][1]);
                    mma16816(acc[mt][2 * ng + 1], a[mt], bh[ng][2], bh[ng][3]);
                    mma16816(acc[mt][2 * ng + 0], a[mt], bl[ng][0], bl[ng][1]);
                    mma16816(acc[mt][2 * ng + 1], a[mt], bl[ng][2], bl[ng][3]);
                }
        }
        __syncthreads();
    }

    const int lr = lid >> 2;
    const int lc = (lid & 3) * 2;
#pragma unroll
    for (int mt = 0; mt < 2; mt++) {
#pragma unroll
        for (int rr = 0; rr < 2; rr++) {
            const int m = m0 + warp_m + mt * 16 + lr + rr * 8;
#pragma unroll
            for (int nt = 0; nt < 8; nt++) {
                const int n = warp_n + nt * 8 + lc;
                float2 v;
                v.x = acc[mt][nt][2 * rr + 0] + bias[n0 + n];
                v.y = acc[mt][nt][2 * rr + 1] + bias[n0 + n + 1];
                size_t addr;
                if (MODE == 0) {
                    const size_t ldc = (size_t)gridDim.y * 128;
                    addr = (size_t)m * ldc + n0 + n;
                } else {
                    int t = m & (TT - 1), bb = m >> 8;
                    int gcol = n0 + n;
                    int gq = gcol >> 10, gj = gcol & 1023;
                    addr = (((size_t)t * 128 + (gj >> 3)) * 64 + bb) * 32 + ((gq << 3) | (gj & 7));
                }
                *reinterpret_cast<float2*>(C + addr) = v;
            }
        }
    }
}
#define GEMM_SMEM (2 * 3 * TILE_B2)

// ---------------- persistent recurrence v9 (byte-identical to R13) ----------------
// SMEM: Whh hi 64K | Whh lo 64K | h stream 3 x 32K (partials overlap stage area) = 229376
#define S_WHH_H 0
#define S_WHH_L 65536
#define S_HSTR  131072
#define S_PART  131072
#define PPITCH  136
#define PGRP    8704
#define S_TOTAL 229376

__global__ void __launch_bounds__(256, 1)
lstm_rec(const float* __restrict__ gx,
         const __half* __restrict__ WhhH, const __half* __restrict__ WhhL,
         __half* __restrict__ h0buf, __half* __restrict__ h1buf,
         const float* __restrict__ cell_init,
         __half* __restrict__ act,
         float* __restrict__ outh, float* __restrict__ outc, int do_state)
{
    extern __shared__ __align__(16) char smem[];
    const uint32_t sb = smem_u32(smem);
    const int tid = threadIdx.x;
    const int nt = blockIdx.x;
    const int wid = tid >> 5, lid = tid & 31;
    const int grp = wid >> 1;        // k-group 0..3 (4 kslots per 256-col chunk)
    const int wm  = wid & 1;         // m-half

    // ---- Whh slice into smem ----
#pragma unroll 1
    for (int it = 0; it < 32; it++) {
        int s = it * 256 + tid;
        int type = s >> 12, idx = s & 4095;
        int row = idx >> 7, seg = idx & 127;
        int grow = (row >> 3) * 1024 + nt * 8 + (row & 7);
        const __half* src = (type ? WhhL : WhhH) + (size_t)grow * 1024 + seg * 8;
        uint32_t dst = sb + (type ? S_WHH_L : S_WHH_H)
                     + (uint32_t)(row * 2048 + ((seg ^ (row & 7)) << 4));
        cp16(dst, src);
    }
    asm volatile("cp.async.commit_group;" ::: "memory");
    asm volatile("cp.async.wait_group 0;" ::: "memory");
    __syncthreads();

    const int q = lid >> 3, i8 = lid & 7;
    const int a_row = (q & 1) * 8 + i8, a_k8 = (q >> 1) * 8;
    const int b_row = (q >> 1) * 8 + i8, b_k8 = (q & 1) * 8;

    // fused reduce+gates mapping: thread owns (batch rb, hidden pair 2*c4)
    const int rb = tid >> 2;         // batch 0..63
    const int c4 = tid & 3;          // gj = 2*c4
    const int gj = 2 * c4;
    float cst0 = cell_init[rb * HH + nt * 8 + gj];
    float cst1 = cell_init[rb * HH + nt * 8 + gj + 1];

#pragma unroll 1
    for (int t = 0; t < TT; t++) {
        const __half* hr = (t & 1) ? h1buf : h0buf;
        __half* hw = (t & 1) ? h0buf : h1buf;

        // prefetch gx[t] (hidden under mma phase)
        const float* gxt = gx + (((size_t)t * 128 + nt) * 64 + rb) * 32;
        float2 xi = __ldcg(reinterpret_cast<const float2*>(gxt + gj));
        float2 xf = __ldcg(reinterpret_cast<const float2*>(gxt + 8 + gj));
        float2 xg = __ldcg(reinterpret_cast<const float2*>(gxt + 16 + gj));
        float2 xo = __ldcg(reinterpret_cast<const float2*>(gxt + 24 + gj));

        // load one 256-col h chunk (64 rows x 512B) into stage (3-stage ring)
        auto load_chunk = [&](int ck, int stage) {
#pragma unroll
            for (int j2 = 0; j2 < 8; j2++) {
                int c = tid + j2 * 256;          // 0..2047 = 64 rows x 32 segs
                int row = c >> 5, seg = c & 31;
                const __half* src = hr + (size_t)row * HH + ck * 256 + seg * 8;
                uint32_t dst = sb + S_HSTR + stage * 32768
                             + (uint32_t)(row * 512 + ((seg ^ (row & 7)) << 4));
                cp16(dst, src);
            }
            asm volatile("cp.async.commit_group;" ::: "memory");
        };

        float acc[2][4][4];
#pragma unroll
        for (int mt = 0; mt < 2; mt++)
#pragma unroll
            for (int n8 = 0; n8 < 4; n8++)
#pragma unroll
                for (int e = 0; e < 4; e++) acc[mt][n8][e] = 0.0f;

        load_chunk(0, 0);
        load_chunk(1, 1);
#pragma unroll 1
        for (int ck = 0; ck < 4; ck++) {
            const int stage = ck % 3;
            if (ck < 2) {
                load_chunk(ck + 2, (ck + 2) % 3);
                asm volatile("cp.async.wait_group 2;" ::: "memory");
            } else if (ck == 2) {
                asm volatile("cp.async.wait_group 1;" ::: "memory");
            } else {
                asm volatile("cp.async.wait_group 0;" ::: "memory");
            }
            __syncthreads();

            const uint32_t ha = sb + S_HSTR + stage * 32768;
#pragma unroll
            for (int s2 = 0; s2 < 4; s2++) {
                const int kslot = grp * 4 + s2;              // 0..15 within 256-col chunk
                uint32_t ah[2][4], wh[2][4], wl[2][4];
#pragma unroll
                for (int mt = 0; mt < 2; mt++) {
                    int row = wm * 32 + mt * 16 + a_row;
                    int seg = (kslot * 16 + a_k8) >> 3;      // 0..31
                    uint32_t off = (uint32_t)(row * 512 + ((seg ^ (row & 7)) << 4));
                    ldm_x4(ah[mt][0], ah[mt][1], ah[mt][2], ah[mt][3], ha + off);
                }
#pragma unroll
                for (int n16 = 0; n16 < 2; n16++) {
                    int wrow = n16 * 16 + b_row;
                    int wseg = (ck * 256 + kslot * 16 + b_k8) >> 3;
                    uint32_t off = (uint32_t)(wrow * 2048 + ((wseg ^ (wrow & 7)) << 4));
                    ldm_x4(wh[n16][0], wh[n16][1], wh[n16][2], wh[n16][3], sb + S_WHH_H + off);
                    ldm_x4(wl[n16][0], wl[n16][1], wl[n16][2], wl[n16][3], sb + S_WHH_L + off);
                }
#pragma unroll
                for (int mt = 0; mt < 2; mt++)
#pragma unroll
                    for (int n16 = 0; n16 < 2; n16++) {
                        mma16816(acc[mt][2 * n16 + 0], ah[mt], wh[n16][0], wh[n16][1]);
                        mma16816(acc[mt][2 * n16 + 1], ah[mt], wh[n16][2], wh[n16][3]);
                        mma16816(acc[mt][2 * n16 + 0], ah[mt], wl[n16][0], wl[n16][1]);
                        mma16816(acc[mt][2 * n16 + 1], ah[mt], wl[n16][2], wl[n16][3]);
                    }
            }
            // no trailing sync: 3-stage ring guarantees safety (R13 analysis)
        }

        // protect S_PART (aliases h-stream stages) from in-flight ldm reads
        __syncthreads();

        // ---- stage per-group partials into idle h-stream smem ----
        {
            const int lr = lid >> 2, lc = lid & 3;
#pragma unroll
            for (int mt = 0; mt < 2; mt++)
#pragma unroll
                for (int n8 = 0; n8 < 4; n8++)
#pragma unroll
                    for (int rr = 0; rr < 2; rr++) {
                        int row = wm * 32 + mt * 16 + lr + rr * 8;
                        int slot = n8 * 4 + lc;
                        uint32_t off = (uint32_t)(S_PART + grp * PGRP + row * PPITCH + slot * 8);
                        *reinterpret_cast<float2*>(smem + off) =
                            make_float2(acc[mt][n8][2 * rr], acc[mt][n8][2 * rr + 1]);
                    }
        }
        __syncthreads();

        // ---- fused 4-way reduce + gates ----
        {
            float sums[8];
#pragma unroll
            for (int e = 0; e < 8; e++) sums[e] = 0.0f;
#pragma unroll
            for (int g = 0; g < 4; g++) {
#pragma unroll
                for (int s = 0; s < 4; s++) {
                    int slot = s * 4 + c4;      // cols {8s+2c4, 8s+2c4+1}
                    uint32_t off = (uint32_t)(S_PART + g * PGRP + rb * PPITCH + slot * 8);
                    float2 p = *reinterpret_cast<const float2*>(smem + off);
                    sums[2 * s] += p.x;
                    sums[2 * s + 1] += p.y;
                }
            }
            float gi0 = sums[0] + xi.x, gi1 = sums[1] + xi.y;
            float gf0 = sums[2] + xf.x, gf1 = sums[3] + xf.y;
            float gg0 = sums[4] + xg.x, gg1 = sums[5] + xg.y;
            float go0 = sums[6] + xo.x, go1 = sums[7] + xo.y;

            cst0 = sigmoidf_(gf0) * cst0 + sigmoidf_(gi0) * tanhf(gg0);
            cst1 = sigmoidf_(gf1) * cst1 + sigmoidf_(gi1) * tanhf(gg1);
            float h0 = sigmoidf_(go0) * tanhf(cst0);
            float h1 = sigmoidf_(go1) * tanhf(cst1);

            __half2 hv = {__float2half(h0), __float2half(h1)};

            const int hidx = rb * HH + nt * 8 + gj;
            *reinterpret_cast<__half2*>(hw + hidx) = hv;
            const size_t aidx = ((size_t)rb * TT + t) * HH + nt * 8 + gj;
            *reinterpret_cast<__half2*>(act + aidx) = hv;
            if (do_state && t == TT - 1) {
                *reinterpret_cast<float2*>(outh + hidx) = make_float2(h0, h1);
                *reinterpret_cast<float2*>(outc + hidx) = make_float2(cst0, cst1);
            }
        }

        grid_barrier();
    }
}

// ---------------- launch ----------------
extern "C" void kernel_launch(void* const* d_in, const int* in_sizes, int n_in,
                              void* d_out, int out_size)
{
    const float* x      = (const float*)d_in[0];
    const float* hidden = (const float*)d_in[1];
    const float* cell   = (const float*)d_in[2];
    const float* W_ih   = (const float*)d_in[3];
    const float* W_hh   = (const float*)d_in[4];
    const float* bvec   = (const float*)d_in[5];
    const float* W_out  = (const float*)d_in[6];
    const float* b_out  = (const float*)d_in[7];
    float* out = (float*)d_out;

    float* p_gx;
    cudaGetSymbolAddress((void**)&p_gx, g_gx);
    __half *p_act, *p_h;
    __half *p_wih_h, *p_wih_l, *p_whh_h, *p_whh_l, *p_wout_h, *p_wout_l;
    cudaGetSymbolAddress((void**)&p_act, g_act);
    cudaGetSymbolAddress((void**)&p_h, g_h);
    cudaGetSymbolAddress((void**)&p_wih_h, g_wih_h);
    cudaGetSymbolAddress((void**)&p_wih_l, g_wih_l);
    cudaGetSymbolAddress((void**)&p_whh_h, g_whh_h);
    cudaGetSymbolAddress((void**)&p_whh_l, g_whh_l);
    cudaGetSymbolAddress((void**)&p_wout_h, g_wout_h);
    cudaGetSymbolAddress((void**)&p_wout_l, g_wout_l);

    cudaFuncSetAttribute(lstm_rec, cudaFuncAttributeMaxDynamicSharedMemorySize, S_TOTAL);
    cudaFuncSetAttribute(gemm_hmma<0>, cudaFuncAttributeMaxDynamicSharedMemorySize, GEMM_SMEM);
    cudaFuncSetAttribute(gemm_hmma<1>, cudaFuncAttributeMaxDynamicSharedMemorySize, GEMM_SMEM);

    const size_t LOGITS = (size_t)BB * TT * DD;
    const size_t STATE  = (size_t)BB * HH;
    const int write_state = ((size_t)out_size >= LOGITS + 2 * LNUM * STATE) ? 1 : 0;

    {
        int n4 = (LNUM * G4 * HH) / 4;
        splitw_f16<<<(n4 + 255) / 256, 256>>>(W_ih, p_wih_h, p_wih_l, n4);
        splitw_f16<<<(n4 + 255) / 256, 256>>>(W_hh, p_whh_h, p_whh_l, n4);
        int m4 = (DD * HH) / 4;
        splitw_f16<<<(m4 + 255) / 256, 256>>>(W_out, p_wout_h, p_wout_l, m4);
    }
    {
        int n4 = (BB * TT * HH) / 4;
        conv_f16<<<(n4 + 255) / 256, 256>>>(x, p_act, n4);
    }

    for (int l = 0; l < LNUM; l++) {
        gemm_hmma<1><<<dim3(128, 32), 256, GEMM_SMEM>>>(
            p_act,
            p_wih_h + (size_t)l * G4 * HH, p_wih_l + (size_t)l * G4 * HH,
            bvec + (size_t)l * G4, p_gx);

        {
            int n4 = (int)(STATE / 4);
            conv_f16<<<(n4 + 255) / 256, 256>>>(hidden + (size_t)l * STATE, p_h, n4);
        }

        lstm_rec<<<NBLK, 256, S_TOTAL>>>(
            p_gx,
            p_whh_h + (size_t)l * G4 * HH, p_whh_l + (size_t)l * G4 * HH,
            p_h, p_h + STATE,
            cell + (size_t)l * STATE,
            p_act,
            out + LOGITS + (size_t)l * STATE,
            out + LOGITS + LNUM * STATE + (size_t)l * STATE,
            write_state);
    }

    gemm_hmma<0><<<dim3(128, 8), 256, GEMM_SMEM>>>(
        p_act, p_wout_h, p_wout_l, b_out, out);
}

// round 17
// speedup vs baseline: 1.4127x; 1.4127x over previous
#include <cuda_runtime.h>
#include <cuda_fp16.h>
#include <math.h>
#include <stdint.h>

// Problem constants
#define LNUM 4
#define BB   64
#define TT   256
#define HH   1024
#define DD   1024
#define G4   4096
#define NBLK 128

// ---------------- scratch (device globals) ----------------
__device__ float g_gx[(size_t)TT * BB * G4];               // [t][nt][b][32] block-local layout
__device__ unsigned long long g_barctr;

__device__ __half g_act[(size_t)BB * TT * HH];             // fp16 single-term activations
__device__ __half g_h[2][BB * HH];                         // h ping-pong, fp16 single
__device__ __half g_wih_h[(size_t)LNUM * G4 * HH];
__device__ __half g_wih_l[(size_t)LNUM * G4 * HH];
__device__ __half g_whh_h[(size_t)LNUM * G4 * HH];
__device__ __half g_whh_l[(size_t)LNUM * G4 * HH];
__device__ __half g_wout_h[(size_t)DD * HH];
__device__ __half g_wout_l[(size_t)DD * HH];

// ---------------- helpers ----------------
__device__ __forceinline__ uint32_t smem_u32(const void* p) {
    uint32_t a;
    asm("{ .reg .u64 t; cvta.to.shared.u64 t, %1; cvt.u32.u64 %0, t; }" : "=r"(a) : "l"(p));
    return a;
}
__device__ __forceinline__ float sigmoidf_(float x) { return 1.0f / (1.0f + expf(-x)); }

__device__ __forceinline__ void ldm_x4(uint32_t& r0, uint32_t& r1, uint32_t& r2, uint32_t& r3, uint32_t addr) {
    asm volatile("ldmatrix.sync.aligned.m8n8.x4.shared.b16 {%0,%1,%2,%3}, [%4];"
                 : "=r"(r0), "=r"(r1), "=r"(r2), "=r"(r3) : "r"(addr));
}
__device__ __forceinline__ void mma16816(float* d, const uint32_t* a, uint32_t b0, uint32_t b1) {
    asm volatile("mma.sync.aligned.m16n8k16.row.col.f32.f16.f16.f32 "
                 "{%0,%1,%2,%3}, {%4,%5,%6,%7}, {%8,%9}, {%0,%1,%2,%3};"
                 : "+f"(d[0]), "+f"(d[1]), "+f"(d[2]), "+f"(d[3])
                 : "r"(a[0]), "r"(a[1]), "r"(a[2]), "r"(a[3]), "r"(b0), "r"(b1));
}
__device__ __forceinline__ void cp16(uint32_t saddr, const void* gaddr) {
    asm volatile("cp.async.cg.shared.global [%0], [%1], 16;" :: "r"(saddr), "l"(gaddr));
}

// ---------------- grid barrier (monotonic ticket) ----------------
__device__ __forceinline__ void grid_barrier() {
    __syncthreads();
    if (threadIdx.x == 0) {
        __threadfence();
        unsigned long long ticket = atomicAdd(&g_barctr, 1ull);
        unsigned long long target = (ticket / NBLK + 1ull) * NBLK;
        while (*(volatile unsigned long long*)&g_barctr < target) __nanosleep(32);
        __threadfence();
    }
    __syncthreads();
}

// ---------------- fp32 -> fp16 hi/lo weight split ----------------
__global__ void __launch_bounds__(256)
splitw_f16(const float* __restrict__ in, __half* __restrict__ hi,
           __half* __restrict__ lo, int n4)
{
    int i = blockIdx.x * blockDim.x + threadIdx.x;
    if (i >= n4) return;
    float4 v = reinterpret_cast<const float4*>(in)[i];
    __half h0 = __float2half(v.x), h1 = __float2half(v.y);
    __half h2 = __float2half(v.z), h3 = __float2half(v.w);
    __half l0 = __float2half(v.x - __half2float(h0));
    __half l1 = __float2half(v.y - __half2float(h1));
    __half l2 = __float2half(v.z - __half2float(h2));
    __half l3 = __float2half(v.w - __half2float(h3));
    __half2 hv0 = {h0, h1}, hv1 = {h2, h3};
    __half2 lv0 = {l0, l1}, lv1 = {l2, l3};
    reinterpret_cast<__half2*>(hi)[2 * i] = hv0;
    reinterpret_cast<__half2*>(hi)[2 * i + 1] = hv1;
    reinterpret_cast<__half2*>(lo)[2 * i] = lv0;
    reinterpret_cast<__half2*>(lo)[2 * i + 1] = lv1;
}

// ---------------- fp32 -> fp16 single conversion ----------------
__global__ void __launch_bounds__(256)
conv_f16(const float* __restrict__ in, __half* __restrict__ out, int n4)
{
    int i = blockIdx.x * blockDim.x + threadIdx.x;
    if (i >= n4) return;
    float4 v = reinterpret_cast<const float4*>(in)[i];
    __half2 o0 = {__float2half(v.x), __float2half(v.y)};
    __half2 o1 = {__float2half(v.z), __float2half(v.w)};
    reinterpret_cast<__half2*>(out)[2 * i] = o0;
    reinterpret_cast<__half2*>(out)[2 * i + 1] = o1;
}

// ---------------- HMMA fp16 GEMM: C = A*(Wh+Wl)^T + bias (fp32 acc, 1 CTA/SM) ----------------
#define GK      1024
#define PITCH   40
#define TILE_B2 10240

template<int MODE>
__global__ void __launch_bounds__(256, 1)
gemm_hmma(const __half* __restrict__ A,
          const __half* __restrict__ Bh, const __half* __restrict__ Bl,
          const float* __restrict__ bias, float* __restrict__ C)
{
    extern __shared__ __align__(16) char smem[];
    const uint32_t s0 = smem_u32(smem);

    const int tid = threadIdx.x;
    const int wid = tid >> 5;
    const int lid = tid & 31;
    const int m0 = blockIdx.x * 128;
    const int n0 = blockIdx.y * 128;
    const int warp_m = (wid >> 1) * 32;
    const int warp_n = (wid & 1) * 64;

    auto preload = [&](int s, int kb) {
        const uint32_t base = s0 + (uint32_t)s * (3 * TILE_B2);
#pragma unroll
        for (int j = 0; j < 6; j++) {
            int c = tid + j * 256;
            int tsel = c >> 9, idx = c & 511;
            int row = idx >> 2, seg = idx & 3;
            const __half* src;
            if (tsel == 0)      src = A  + (size_t)(m0 + row) * GK + kb + seg * 8;
            else if (tsel == 1) src = Bh + (size_t)(n0 + row) * GK + kb + seg * 8;
            else                src = Bl + (size_t)(n0 + row) * GK + kb + seg * 8;
            uint32_t dst = base + (uint32_t)tsel * TILE_B2 + (uint32_t)(row * 80 + seg * 16);
            cp16(dst, src);
        }
        asm volatile("cp.async.commit_group;" ::: "memory");
    };

    const int q = lid >> 3, i8 = lid & 7;
    const int a_row = (q & 1) * 8 + i8;
    const int a_k8  = (q >> 1) * 8;
    const int b_row = (q >> 1) * 8 + i8;
    const int b_k8  = (q & 1) * 8;

    float acc[2][8][4];
#pragma unroll
    for (int mt = 0; mt < 2; mt++)
#pragma unroll
        for (int nt = 0; nt < 8; nt++)
#pragma unroll
            for (int e = 0; e < 4; e++) acc[mt][nt][e] = 0.0f;

    constexpr int NIT = 32;
    preload(0, 0);

#pragma unroll 1
    for (int it = 0; it < NIT; it++) {
        const int s = it & 1;
        if (it + 1 < NIT) {
            preload(s ^ 1, (it + 1) * 32);
            asm volatile("cp.async.wait_group 1;" ::: "memory");
        } else {
            asm volatile("cp.async.wait_group 0;" ::: "memory");
        }
        __syncthreads();

        const uint32_t sa  = s0 + (uint32_t)s * (3 * TILE_B2);
        const uint32_t sbh = sa + TILE_B2;
        const uint32_t sbl = sa + 2 * TILE_B2;
#pragma unroll
        for (int kk = 0; kk < 32; kk += 16) {
            uint32_t a[2][4], bh[4][4], bl[4][4];
#pragma unroll
            for (int mt = 0; mt < 2; mt++) {
                uint32_t addr = sa + (uint32_t)((warp_m + mt * 16 + a_row) * 80 + (kk + a_k8) * 2);
                ldm_x4(a[mt][0], a[mt][1], a[mt][2], a[mt][3], addr);
            }
#pragma unroll
            for (int ng = 0; ng < 4; ng++) {
                uint32_t off = (uint32_t)((warp_n + ng * 16 + b_row) * 80 + (kk + b_k8) * 2);
                ldm_x4(bh[ng][0], bh[ng][1], bh[ng][2], bh[ng][3], sbh + off);
                ldm_x4(bl[ng][0], bl[ng][1], bl[ng][2], bl[ng][3], sbl + off);
            }
#pragma unroll
            for (int mt = 0; mt < 2; mt++)
#pragma unroll
                for (int ng = 0; ng < 4; ng++) {
                    mma16816(acc[mt][2 * ng + 0], a[mt], bh[ng][0], bh[ng][1]);
                    mma16816(acc[mt][2 * ng + 1], a[mt], bh[ng][2], bh[ng][3]);
                    mma16816(acc[mt][2 * ng + 0], a[mt], bl[ng][0], bl[ng][1]);
                    mma16816(acc[mt][2 * ng + 1], a[mt], bl[ng][2], bl[ng][3]);
                }
        }
        __syncthreads();
    }

    const int lr = lid >> 2;
    const int lc = (lid & 3) * 2;
#pragma unroll
    for (int mt = 0; mt < 2; mt++) {
#pragma unroll
        for (int rr = 0; rr < 2; rr++) {
            const int m = m0 + warp_m + mt * 16 + lr + rr * 8;
#pragma unroll
            for (int nt = 0; nt < 8; nt++) {
                const int n = warp_n + nt * 8 + lc;
                float2 v;
                v.x = acc[mt][nt][2 * rr + 0] + bias[n0 + n];
                v.y = acc[mt][nt][2 * rr + 1] + bias[n0 + n + 1];
                size_t addr;
                if (MODE == 0) {
                    const size_t ldc = (size_t)gridDim.y * 128;
                    addr = (size_t)m * ldc + n0 + n;
                } else {
                    int t = m & (TT - 1), bb = m >> 8;
                    int gcol = n0 + n;
                    int gq = gcol >> 10, gj = gcol & 1023;
                    addr = (((size_t)t * 128 + (gj >> 3)) * 64 + bb) * 32 + ((gq << 3) | (gj & 7));
                }
                *reinterpret_cast<float2*>(C + addr) = v;
            }
        }
    }
}
#define GEMM_SMEM (2 * 3 * TILE_B2)

// ---------------- persistent recurrence v9 (R13 proven best) ----------------
// SMEM: Whh hi 64K | Whh lo 64K | h stream 3 x 32K (partials overlap stage area) = 229376
#define S_WHH_H 0
#define S_WHH_L 65536
#define S_HSTR  131072
#define S_PART  131072
#define PPITCH  136
#define PGRP    8704
#define S_TOTAL 229376

__global__ void __launch_bounds__(256, 1)
lstm_rec(const float* __restrict__ gx,
         const __half* __restrict__ WhhH, const __half* __restrict__ WhhL,
         __half* __restrict__ h0buf, __half* __restrict__ h1buf,
         const float* __restrict__ cell_init,
         __half* __restrict__ act,
         float* __restrict__ outh, float* __restrict__ outc, int do_state)
{
    extern __shared__ __align__(16) char smem[];
    const uint32_t sb = smem_u32(smem);
    const int tid = threadIdx.x;
    const int nt = blockIdx.x;
    const int wid = tid >> 5, lid = tid & 31;
    const int grp = wid >> 1;        // k-group 0..3 (4 kslots per 256-col chunk)
    const int wm  = wid & 1;         // m-half

    // ---- Whh slice into smem ----
#pragma unroll 1
    for (int it = 0; it < 32; it++) {
        int s = it * 256 + tid;
        int type = s >> 12, idx = s & 4095;
        int row = idx >> 7, seg = idx & 127;
        int grow = (row >> 3) * 1024 + nt * 8 + (row & 7);
        const __half* src = (type ? WhhL : WhhH) + (size_t)grow * 1024 + seg * 8;
        uint32_t dst = sb + (type ? S_WHH_L : S_WHH_H)
                     + (uint32_t)(row * 2048 + ((seg ^ (row & 7)) << 4));
        cp16(dst, src);
    }
    asm volatile("cp.async.commit_group;" ::: "memory");
    asm volatile("cp.async.wait_group 0;" ::: "memory");
    __syncthreads();

    const int q = lid >> 3, i8 = lid & 7;
    const int a_row = (q & 1) * 8 + i8, a_k8 = (q >> 1) * 8;
    const int b_row = (q >> 1) * 8 + i8, b_k8 = (q & 1) * 8;

    // fused reduce+gates mapping: thread owns (batch rb, hidden pair 2*c4)
    const int rb = tid >> 2;         // batch 0..63
    const int c4 = tid & 3;          // gj = 2*c4
    const int gj = 2 * c4;
    float cst0 = cell_init[rb * HH + nt * 8 + gj];
    float cst1 = cell_init[rb * HH + nt * 8 + gj + 1];

#pragma unroll 1
    for (int t = 0; t < TT; t++) {
        const __half* hr = (t & 1) ? h1buf : h0buf;
        __half* hw = (t & 1) ? h0buf : h1buf;

        // prefetch gx[t] (hidden under mma phase)
        const float* gxt = gx + (((size_t)t * 128 + nt) * 64 + rb) * 32;
        float2 xi = __ldcg(reinterpret_cast<const float2*>(gxt + gj));
        float2 xf = __ldcg(reinterpret_cast<const float2*>(gxt + 8 + gj));
        float2 xg = __ldcg(reinterpret_cast<const float2*>(gxt + 16 + gj));
        float2 xo = __ldcg(reinterpret_cast<const float2*>(gxt + 24 + gj));

        // load one 256-col h chunk (64 rows x 512B) into stage (3-stage ring)
        auto load_chunk = [&](int ck, int stage) {
#pragma unroll
            for (int j2 = 0; j2 < 8; j2++) {
                int c = tid + j2 * 256;          // 0..2047 = 64 rows x 32 segs
                int row = c >> 5, seg = c & 31;
                const __half* src = hr + (size_t)row * HH + ck * 256 + seg * 8;
                uint32_t dst = sb + S_HSTR + stage * 32768
                             + (uint32_t)(row * 512 + ((seg ^ (row & 7)) << 4));
                cp16(dst, src);
            }
            asm volatile("cp.async.commit_group;" ::: "memory");
        };

        float acc[2][4][4];
#pragma unroll
        for (int mt = 0; mt < 2; mt++)
#pragma unroll
            for (int n8 = 0; n8 < 4; n8++)
#pragma unroll
                for (int e = 0; e < 4; e++) acc[mt][n8][e] = 0.0f;

        load_chunk(0, 0);
        load_chunk(1, 1);
#pragma unroll 1
        for (int ck = 0; ck < 4; ck++) {
            const int stage = ck % 3;
            if (ck < 2) {
                load_chunk(ck + 2, (ck + 2) % 3);
                asm volatile("cp.async.wait_group 2;" ::: "memory");
            } else if (ck == 2) {
                asm volatile("cp.async.wait_group 1;" ::: "memory");
            } else {
                asm volatile("cp.async.wait_group 0;" ::: "memory");
            }
            __syncthreads();

            const uint32_t ha = sb + S_HSTR + stage * 32768;
#pragma unroll
            for (int s2 = 0; s2 < 4; s2++) {
                const int kslot = grp * 4 + s2;              // 0..15 within 256-col chunk
                uint32_t ah[2][4], wh[2][4], wl[2][4];
#pragma unroll
                for (int mt = 0; mt < 2; mt++) {
                    int row = wm * 32 + mt * 16 + a_row;
                    int seg = (kslot * 16 + a_k8) >> 3;      // 0..31
                    uint32_t off = (uint32_t)(row * 512 + ((seg ^ (row & 7)) << 4));
                    ldm_x4(ah[mt][0], ah[mt][1], ah[mt][2], ah[mt][3], ha + off);
                }
#pragma unroll
                for (int n16 = 0; n16 < 2; n16++) {
                    int wrow = n16 * 16 + b_row;
                    int wseg = (ck * 256 + kslot * 16 + b_k8) >> 3;
                    uint32_t off = (uint32_t)(wrow * 2048 + ((wseg ^ (wrow & 7)) << 4));
                    ldm_x4(wh[n16][0], wh[n16][1], wh[n16][2], wh[n16][3], sb + S_WHH_H + off);
                    ldm_x4(wl[n16][0], wl[n16][1], wl[n16][2], wl[n16][3], sb + S_WHH_L + off);
                }
#pragma unroll
                for (int mt = 0; mt < 2; mt++)
#pragma unroll
                    for (int n16 = 0; n16 < 2; n16++) {
                        mma16816(acc[mt][2 * n16 + 0], ah[mt], wh[n16][0], wh[n16][1]);
                        mma16816(acc[mt][2 * n16 + 1], ah[mt], wh[n16][2], wh[n16][3]);
                        mma16816(acc[mt][2 * n16 + 0], ah[mt], wl[n16][0], wl[n16][1]);
                        mma16816(acc[mt][2 * n16 + 1], ah[mt], wl[n16][2], wl[n16][3]);
                    }
            }
            // no trailing sync: 3-stage ring guarantees safety (R13 analysis)
        }

        // protect S_PART (aliases h-stream stages) from in-flight ldm reads
        __syncthreads();

        // ---- stage per-group partials into idle h-stream smem ----
        {
            const int lr = lid >> 2, lc = lid & 3;
#pragma unroll
            for (int mt = 0; mt < 2; mt++)
#pragma unroll
                for (int n8 = 0; n8 < 4; n8++)
#pragma unroll
                    for (int rr = 0; rr < 2; rr++) {
                        int row = wm * 32 + mt * 16 + lr + rr * 8;
                        int slot = n8 * 4 + lc;
                        uint32_t off = (uint32_t)(S_PART + grp * PGRP + row * PPITCH + slot * 8);
                        *reinterpret_cast<float2*>(smem + off) =
                            make_float2(acc[mt][n8][2 * rr], acc[mt][n8][2 * rr + 1]);
                    }
        }
        __syncthreads();

        // ---- fused 4-way reduce + gates ----
        {
            float sums[8];
#pragma unroll
            for (int e = 0; e < 8; e++) sums[e] = 0.0f;
#pragma unroll
            for (int g = 0; g < 4; g++) {
#pragma unroll
                for (int s = 0; s < 4; s++) {
                    int slot = s * 4 + c4;      // cols {8s+2c4, 8s+2c4+1}
                    uint32_t off = (uint32_t)(S_PART + g * PGRP + rb * PPITCH + slot * 8);
                    float2 p = *reinterpret_cast<const float2*>(smem + off);
                    sums[2 * s] += p.x;
                    sums[2 * s + 1] += p.y;
                }
            }
            float gi0 = sums[0] + xi.x, gi1 = sums[1] + xi.y;
            float gf0 = sums[2] + xf.x, gf1 = sums[3] + xf.y;
            float gg0 = sums[4] + xg.x, gg1 = sums[5] + xg.y;
            float go0 = sums[6] + xo.x, go1 = sums[7] + xo.y;

            cst0 = sigmoidf_(gf0) * cst0 + sigmoidf_(gi0) * tanhf(gg0);
            cst1 = sigmoidf_(gf1) * cst1 + sigmoidf_(gi1) * tanhf(gg1);
            float h0 = sigmoidf_(go0) * tanhf(cst0);
            float h1 = sigmoidf_(go1) * tanhf(cst1);

            __half2 hv = {__float2half(h0), __float2half(h1)};

            const int hidx = rb * HH + nt * 8 + gj;
            *reinterpret_cast<__half2*>(hw + hidx) = hv;
            const size_t aidx = ((size_t)rb * TT + t) * HH + nt * 8 + gj;
            *reinterpret_cast<__half2*>(act + aidx) = hv;
            if (do_state && t == TT - 1) {
                *reinterpret_cast<float2*>(outh + hidx) = make_float2(h0, h1);
                *reinterpret_cast<float2*>(outc + hidx) = make_float2(cst0, cst1);
            }
        }

        grid_barrier();
    }
}

// ---------------- launch ----------------
extern "C" void kernel_launch(void* const* d_in, const int* in_sizes, int n_in,
                              void* d_out, int out_size)
{
    const float* x      = (const float*)d_in[0];
    const float* hidden = (const float*)d_in[1];
    const float* cell   = (const float*)d_in[2];
    const float* W_ih   = (const float*)d_in[3];
    const float* W_hh   = (const float*)d_in[4];
    const float* bvec   = (const float*)d_in[5];
    const float* W_out  = (const float*)d_in[6];
    const float* b_out  = (const float*)d_in[7];
    float* out = (float*)d_out;

    float* p_gx;
    cudaGetSymbolAddress((void**)&p_gx, g_gx);
    __half *p_act, *p_h;
    __half *p_wih_h, *p_wih_l, *p_whh_h, *p_whh_l, *p_wout_h, *p_wout_l;
    cudaGetSymbolAddress((void**)&p_act, g_act);
    cudaGetSymbolAddress((void**)&p_h, g_h);
    cudaGetSymbolAddress((void**)&p_wih_h, g_wih_h);
    cudaGetSymbolAddress((void**)&p_wih_l, g_wih_l);
    cudaGetSymbolAddress((void**)&p_whh_h, g_whh_h);
    cudaGetSymbolAddress((void**)&p_whh_l, g_whh_l);
    cudaGetSymbolAddress((void**)&p_wout_h, g_wout_h);
    cudaGetSymbolAddress((void**)&p_wout_l, g_wout_l);

    cudaFuncSetAttribute(lstm_rec, cudaFuncAttributeMaxDynamicSharedMemorySize, S_TOTAL);
    cudaFuncSetAttribute(gemm_hmma<0>, cudaFuncAttributeMaxDynamicSharedMemorySize, GEMM_SMEM);
    cudaFuncSetAttribute(gemm_hmma<1>, cudaFuncAttributeMaxDynamicSharedMemorySize, GEMM_SMEM);

    const size_t LOGITS = (size_t)BB * TT * DD;
    const size_t STATE  = (size_t)BB * HH;
    const int write_state = ((size_t)out_size >= LOGITS + 2 * LNUM * STATE) ? 1 : 0;

    {
        int n4 = (LNUM * G4 * HH) / 4;
        splitw_f16<<<(n4 + 255) / 256, 256>>>(W_ih, p_wih_h, p_wih_l, n4);
        splitw_f16<<<(n4 + 255) / 256, 256>>>(W_hh, p_whh_h, p_whh_l, n4);
        int m4 = (DD * HH) / 4;
        splitw_f16<<<(m4 + 255) / 256, 256>>>(W_out, p_wout_h, p_wout_l, m4);
    }
    {
        int n4 = (BB * TT * HH) / 4;
        conv_f16<<<(n4 + 255) / 256, 256>>>(x, p_act, n4);
    }

    for (int l = 0; l < LNUM; l++) {
        gemm_hmma<1><<<dim3(128, 32), 256, GEMM_SMEM>>>(
            p_act,
            p_wih_h + (size_t)l * G4 * HH, p_wih_l + (size_t)l * G4 * HH,
            bvec + (size_t)l * G4, p_gx);

        {
            int n4 = (int)(STATE / 4);
            conv_f16<<<(n4 + 255) / 256, 256>>>(hidden + (size_t)l * STATE, p_h, n4);
        }

        lstm_rec<<<NBLK, 256, S_TOTAL>>>(
            p_gx,
            p_whh_h + (size_t)l * G4 * HH, p_whh_l + (size_t)l * G4 * HH,
            p_h, p_h + STATE,
            cell + (size_t)l * STATE,
            p_act,
            out + LOGITS + (size_t)l * STATE,
            out + LOGITS + LNUM * STATE + (size_t)l * STATE,
            write_state);
    }

    gemm_hmma<0><<<dim3(128, 8), 256, GEMM_SMEM>>>(
        p_act, p_wout_h, p_wout_l, b_out, out);
}